// round 16
// baseline (speedup 1.0000x reference)
#include <cuda_runtime.h>
#include <cuda_bf16.h>
#include <cstdint>

#define BDIM   16384
#define FDIM   256
#define BOND   16

#if defined(__CUDA_ARCH__) && (defined(__CUDA_ARCH_FEAT_SM103_ALL) || defined(__CUDA_ARCH_SPECIFIC__))
#define TC_PATH 1
#else
#define TC_PATH 0
#endif

// 130 KB dynamic smem -> exactly one CTA per SM (TMEM 512-col alloc safety).
#define SMEM_DYN (130 * 1024)

__device__ float g_xT[FDIM * BDIM];
__device__ float g_bufA[128 * BDIM * BOND];
__device__ float g_bufB[64  * BDIM * BOND];

#if TC_PATH
__device__ __forceinline__ uint32_t smem_u32(const void* p) {
    uint32_t a;
    asm("{ .reg .u64 t; cvta.to.shared.u64 t, %1; cvt.u32.u64 %0, t; }" : "=r"(a) : "l"(p));
    return a;
}
__device__ __forceinline__ uint32_t elect_one() {
    uint32_t p;
    asm volatile("{ .reg .pred p; elect.sync _|p, 0xFFFFFFFF; selp.b32 %0, 1, 0, p; }" : "=r"(p));
    return p;
}
#define TC_ALLOC(smem_addr, n) \
    asm volatile("tcgen05.alloc.cta_group::1.sync.aligned.shared::cta.b32 [%0], %1;" \
                 :: "r"(smem_addr), "r"((uint32_t)(n)) : "memory")
#define TC_DEALLOC(tmem, n) \
    asm volatile("tcgen05.dealloc.cta_group::1.sync.aligned.b32 %0, %1;" :: "r"(tmem), "r"((uint32_t)(n)))
#define TC_RELINQ() \
    asm volatile("tcgen05.relinquish_alloc_permit.cta_group::1.sync.aligned;")
#define TC_WAIT_ST() asm volatile("tcgen05.wait::st.sync.aligned;" ::: "memory")
#define TC_WAIT_LD() asm volatile("tcgen05.wait::ld.sync.aligned;" ::: "memory")
#define TC_FENCE_BEFORE() asm volatile("tcgen05.fence::before_thread_sync;" ::: "memory")
#define TC_FENCE_AFTER()  asm volatile("tcgen05.fence::after_thread_sync;" ::: "memory")
#define TC_COMMIT(mbar) \
    asm volatile("tcgen05.commit.cta_group::1.mbarrier::arrive::one.shared::cluster.b64 [%0];" \
                 :: "r"(mbar) : "memory")
#define MBAR_INIT(mbar, cnt) \
    asm volatile("mbarrier.init.shared.b64 [%0], %1;" :: "r"(mbar), "r"((uint32_t)(cnt)) : "memory")
#define MBAR_INVAL(mbar) \
    asm volatile("mbarrier.inval.shared.b64 [%0];" :: "r"(mbar) : "memory")
#define MBAR_WAIT(mbar, parity) do {                                             \
    uint32_t _m = (mbar); uint32_t _p = (parity); uint32_t _done;                \
    asm volatile("{ .reg .pred p; mbarrier.try_wait.parity.acquire.cta.shared::cta.b64 p, [%1], %2;" \
                 " selp.b32 %0, 1, 0, p; }" : "=r"(_done) : "r"(_m), "r"(_p) : "memory"); \
    if (!_done) {                                                                \
        asm volatile("{ .reg .pred P1; WL%=:"                                    \
                     " mbarrier.try_wait.parity.acquire.cta.shared::cta.b64 P1, [%0], %1, 0x989680;" \
                     " @P1 bra.uni WD%=; bra.uni WL%=; WD%=: }"                  \
                     :: "r"(_m), "r"(_p) : "memory");                            \
    } } while (0)

__device__ __forceinline__ void sttm_x32(uint32_t addr, const uint32_t* r) {
    asm volatile(
        "tcgen05.st.sync.aligned.32x32b.x32.b32 [%0], "
        "{%1,%2,%3,%4,%5,%6,%7,%8,%9,%10,%11,%12,%13,%14,%15,%16,"
        "%17,%18,%19,%20,%21,%22,%23,%24,%25,%26,%27,%28,%29,%30,%31,%32};"
        :: "r"(addr),
           "r"(r[0]),"r"(r[1]),"r"(r[2]),"r"(r[3]),"r"(r[4]),"r"(r[5]),"r"(r[6]),"r"(r[7]),
           "r"(r[8]),"r"(r[9]),"r"(r[10]),"r"(r[11]),"r"(r[12]),"r"(r[13]),"r"(r[14]),"r"(r[15]),
           "r"(r[16]),"r"(r[17]),"r"(r[18]),"r"(r[19]),"r"(r[20]),"r"(r[21]),"r"(r[22]),"r"(r[23]),
           "r"(r[24]),"r"(r[25]),"r"(r[26]),"r"(r[27]),"r"(r[28]),"r"(r[29]),"r"(r[30]),"r"(r[31])
        : "memory");
}
__device__ __forceinline__ void ldtm_x8(uint32_t* r, uint32_t addr) {
    asm volatile(
        "tcgen05.ld.sync.aligned.32x32b.x8.b32 "
        "{%0,%1,%2,%3,%4,%5,%6,%7}, [%8];"
        : "=r"(r[0]),"=r"(r[1]),"=r"(r[2]),"=r"(r[3]),
          "=r"(r[4]),"=r"(r[5]),"=r"(r[6]),"=r"(r[7])
        : "r"(addr));
}
__device__ __forceinline__ void mma_f16_ts(uint32_t d_tmem, uint32_t a_tmem,
                                           uint64_t b_desc, uint32_t idesc, bool acc) {
    uint32_t en = acc ? 1u : 0u;
    asm volatile(
        "{ .reg .pred p; setp.ne.u32 p, %5, 0;"
        " tcgen05.mma.cta_group::1.kind::f16 [%0], [%1], %2, %3, {%4,%4,%4,%4}, p; }"
        :: "r"(d_tmem), "r"(a_tmem), "l"(b_desc), "r"(idesc), "r"(0u), "r"(en)
        : "memory");
}
__device__ __forceinline__ uint64_t make_desc(uint32_t smem_addr) {
    return ((uint64_t)2 << 61) | ((uint64_t)1 << 46) | ((uint64_t)64 << 32)
         | ((uint64_t)1 << 16) | (((uint64_t)(smem_addr >> 4)) & 0x3FFF);
}

__device__ __forceinline__ void drain_D_half(float* __restrict__ out, int p, int bp,
                                             uint32_t tDbuf, int half) {
    uint32_t dr[8];
    ldtm_x8(dr, tDbuf + (uint32_t)(half * 8));
    TC_WAIT_LD();
    float4* op = reinterpret_cast<float4*>(out + ((size_t)p * BDIM + bp) * 16 + half * 8);
    op[0] = make_float4(__uint_as_float(dr[0]), __uint_as_float(dr[1]),
                        __uint_as_float(dr[2]), __uint_as_float(dr[3]));
    op[1] = make_float4(__uint_as_float(dr[4]), __uint_as_float(dr[5]),
                        __uint_as_float(dr[6]), __uint_as_float(dr[7]));
}

// Stage W as bf16 hi/lo, N=16 rows x K=256, K-major blocked-atom SW128.
__device__ __forceinline__ void stage_W(const float* __restrict__ W, int p, int kin,
                                        char* sBhi, char* sBlo, int tid) {
    for (int idx = tid; idx < 4096; idx += 512) {
        int k = idx >> 4, d = idx & 15;
        int i = k >> 4, j = k & 15;
        float w = (i < kin && j < kin)
                ? W[(size_t)p * kin * kin * 16 + ((i * kin + j) * 16 + d)] : 0.f;
        __nv_bfloat16 h  = __float2bfloat16(w);
        __nv_bfloat16 lo = __float2bfloat16(w - __bfloat162float(h));
        int atom = (d >> 3) + (k >> 6) * 2;
        uint32_t off = (uint32_t)atom * 1024u + (uint32_t)(d & 7) * 128u + (uint32_t)(k & 63) * 2u;
        uint32_t sw = off ^ ((off >> 3) & 0x70);
        *reinterpret_cast<__nv_bfloat16*>(sBhi + sw) = h;
        *reinterpret_cast<__nv_bfloat16*>(sBlo + sw) = lo;
    }
}

__device__ __forceinline__ void build_z(const float* ll, const float* rr,
                                        uint32_t* zhi, uint32_t* zlo) {
    #pragma unroll
    for (int ii = 0; ii < 4; ++ii) {
        #pragma unroll
        for (int jh = 0; jh < 8; ++jh) {
            float z0 = ll[ii] * rr[2 * jh];
            float z1 = ll[ii] * rr[2 * jh + 1];
            uint32_t h2;
            asm("cvt.rn.bf16x2.f32 %0, %1, %2;" : "=r"(h2) : "f"(z1), "f"(z0));
            float hf0 = __uint_as_float(h2 << 16);
            float hf1 = __uint_as_float(h2 & 0xffff0000u);
            float zl0 = z0 - hf0;
            float zl1 = z1 - hf1;
            uint32_t l2;
            asm("cvt.rn.bf16x2.f32 %0, %1, %2;" : "=r"(l2) : "f"(zl1), "f"(zl0));
            zhi[ii * 8 + jh] = h2;
            zlo[ii * 8 + jh] = l2;
        }
    }
}
#endif // TC_PATH

struct InRegs { float4 lv, r0, r1, r2, r3; };
__device__ __forceinline__ InRegs load_in(const float* __restrict__ in,
                                          int p, int b, int kq) {
    InRegs q;
    const float4* lp = reinterpret_cast<const float4*>(in + ((size_t)(2 * p) * BDIM + b) * 16);
    q.lv = lp[kq];
    const float4* rp = reinterpret_cast<const float4*>(in + ((size_t)(2 * p + 1) * BDIM + b) * 16);
    q.r0 = rp[0]; q.r1 = rp[1]; q.r2 = rp[2]; q.r3 = rp[3];
    return q;
}

// ---------------- x transpose ------------------------------------------------
__global__ __launch_bounds__(256) void tt_transpose(const float* __restrict__ x,
                                                    float* __restrict__ xT) {
    __shared__ float tile[32][33];
    const int c0 = blockIdx.x * 32;
    const int r0 = blockIdx.y * 32;
    #pragma unroll
    for (int k = 0; k < 4; ++k) {
        int r = r0 + threadIdx.y + 8 * k;
        tile[threadIdx.y + 8 * k][threadIdx.x] = x[(size_t)r * FDIM + c0 + threadIdx.x];
    }
    __syncthreads();
    #pragma unroll
    for (int k = 0; k < 4; ++k) {
        int c = c0 + threadIdx.y + 8 * k;
        xT[(size_t)c * BDIM + r0 + threadIdx.x] = tile[threadIdx.x][threadIdx.y + 8 * k];
    }
}

__device__ __forceinline__ void fourier16(float xv, float fmin, float* f) {
    float a = xv * fmin;
    float s1, c1;
    __sincosf(a, &s1, &c1);
    float s2 = 2.f * s1 * c1,       c2 = c1 * c1 - s1 * s1;
    float s3 = s2 * c1 + c2 * s1,   c3 = c2 * c1 - s2 * s1;
    float s4 = s3 * c1 + c3 * s1,   c4 = c3 * c1 - s3 * s1;
    f[0] = 1.f; f[1] = s1; f[2] = s2; f[3] = s3; f[4] = s4;
    f[5] = c1;  f[6] = c2; f[7] = c3; f[8] = c4;
    #pragma unroll
    for (int i = 9; i < 16; ++i) f[i] = 0.f;
}

#if TC_PATH
// TMEM map: Ahi0 = cols 0-127, Ahi1 = 128-255, Alo = 256-383, D = 384-415.
// Shared tile body for both level kernels. Terms ordered lo*Whi FIRST so Alo
// frees after ~1/3 of the MMA; commit #1 (mbar_lo) signals that, commit #2
// (mbar_main) signals full completion (D final + Ahi free).
struct TcCtx {
    uint32_t tmem, mbar_lo, mbar_main;
    uint64_t dhi, dlo;
    int nsteps;
};

__device__ __forceinline__ void tile_body(const TcCtx& c, int t, int NT,
                                          const uint32_t* zhi, const uint32_t* zlo,
                                          bool my_sttm, uint32_t woff, int kq,
                                          int wid, int dhalf,
                                          float* __restrict__ out, int p, int b) {
    const uint32_t IDESC = 0x8040490u;            // F32 acc, bf16, M=128, N=16
    const uint32_t aHi = c.tmem + (uint32_t)((t & 1) * 128);
    const uint32_t aLo = c.tmem + 256u;
    const uint32_t tDbuf  = c.tmem + 384u + (uint32_t)((t & 1) * 16);
    const uint32_t tDprev = c.tmem + 384u + (uint32_t)(((t - 1) & 1) * 16);

    // STTM hi -> double-buffered slot: no wait needed (last reader MMA(t-2),
    // whose completion was consumed by last iteration's mbar_main wait).
    if (my_sttm)
        sttm_x32(aHi + woff + (uint32_t)(kq * 32), zhi);

    // STTM lo -> shared slot: wait for MMA(t-1)'s lo-term (early commit).
    if (t > 0) { MBAR_WAIT(c.mbar_lo, (uint32_t)((t - 1) & 1)); TC_FENCE_AFTER(); }
    if (my_sttm)
        sttm_x32(aLo + woff + (uint32_t)(kq * 32), zlo);
    TC_WAIT_ST();
    TC_FENCE_BEFORE();
    __syncthreads();                              // A(t) fully written

    // Full completion of MMA(t-1): D(t-1) final, Ahi[(t-1)&1] free.
    if (t > 0) { MBAR_WAIT(c.mbar_main, (uint32_t)((t - 1) & 1)); TC_FENCE_AFTER(); }

    if (wid == 8 && elect_one()) {
        TC_FENCE_AFTER();
        // term 1: zlo * Whi   (frees Alo early)
        for (int s = 0; s < c.nsteps; ++s) {
            uint64_t bd = c.dhi + (uint64_t)((s >> 2) * 128 + (s & 3) * 2);
            mma_f16_ts(tDbuf, aLo + (uint32_t)(s * 8), bd, IDESC, s != 0);
        }
        TC_COMMIT(c.mbar_lo);
        // term 2: zhi * Whi ; term 3: zhi * Wlo
        for (int s = 0; s < c.nsteps; ++s) {
            uint64_t bd = c.dhi + (uint64_t)((s >> 2) * 128 + (s & 3) * 2);
            mma_f16_ts(tDbuf, aHi + (uint32_t)(s * 8), bd, IDESC, true);
        }
        for (int s = 0; s < c.nsteps; ++s) {
            uint64_t bd = c.dlo + (uint64_t)((s >> 2) * 128 + (s & 3) * 2);
            mma_f16_ts(tDbuf, aHi + (uint32_t)(s * 8), bd, IDESC, true);
        }
        TC_COMMIT(c.mbar_main);
    }

    // Drain D(t-1) (warps 0-7) while MMA(t) runs.
    if (t > 0 && wid < 8)
        drain_D_half(out, p, b - 128, tDprev, dhalf);
}

__device__ __forceinline__ void tc_epilogue(const TcCtx& c, int NT, int wid, int tid,
                                            int dhalf, float* __restrict__ out,
                                            int p, int blast) {
    MBAR_WAIT(c.mbar_main, (uint32_t)((NT - 1) & 1));
    TC_FENCE_AFTER();
    if (wid < 8)
        drain_D_half(out, p, blast,
                     c.tmem + 384u + (uint32_t)(((NT - 1) & 1) * 16), dhalf);
    __syncthreads();
    if (tid == 0) { MBAR_INVAL(c.mbar_lo); MBAR_INVAL(c.mbar_main); }
    __syncthreads();
    if (wid == 0) { TC_DEALLOC(c.tmem, 512); }
}
#endif

// ---------------- level 0 (tc) -----------------------------------------------
__global__ __launch_bounds__(512) __cluster_dims__(1, 1, 1)
void tt_tc_level0(const float* __restrict__ xT,
                  const float* __restrict__ fminp,
                  const float* __restrict__ W,
                  float* __restrict__ out, int NT) {
    extern __shared__ char dyn[];
#if TC_PATH
    __shared__ uint32_t s_tmem[1];
    __shared__ __align__(16) unsigned long long s_mbar[2];
    char* sBhi = (char*)(((uintptr_t)dyn + 1023) & ~(uintptr_t)1023);
    char* sBlo = sBhi + 8192;

    const int tid = threadIdx.x;
    const int wid = tid >> 5;
    const int row_lane = tid & 127;
    const int kq = tid >> 7;
    const int p = blockIdx.x;
    const int tile0 = blockIdx.y * NT;
    const float fmin = *fminp;

    if (wid == 0) { TC_ALLOC(smem_u32(s_tmem), 512); TC_RELINQ(); }
    if (tid == 0) { MBAR_INIT(smem_u32(&s_mbar[0]), 1); MBAR_INIT(smem_u32(&s_mbar[1]), 1); }
    stage_W(W, p, 9, sBhi, sBlo, tid);
    __syncthreads();

    TcCtx c;
    c.tmem = s_tmem[0];
    c.mbar_lo = smem_u32(&s_mbar[0]);
    c.mbar_main = smem_u32(&s_mbar[1]);
    c.dhi = make_desc(smem_u32(sBhi));
    c.dlo = make_desc(smem_u32(sBlo));
    c.nsteps = 9;
    const uint32_t woff = (uint32_t)(wid & 3) << 21;
    const bool my_sttm = (kq < 3);
    const int dhalf = (wid >> 2) & 1;

    float xl = xT[(size_t)(2 * p) * BDIM + tile0 * 128 + row_lane];
    float xr = xT[(size_t)(2 * p + 1) * BDIM + tile0 * 128 + row_lane];

    for (int t = 0; t < NT; ++t) {
        const int b = (tile0 + t) * 128 + row_lane;

        float rr[16]; fourier16(xr, fmin, rr);
        float fl[16]; fourier16(xl, fmin, fl);
        float ll[4];
        if      (kq == 0) { ll[0]=fl[0]; ll[1]=fl[1]; ll[2]=fl[2]; ll[3]=fl[3]; }
        else if (kq == 1) { ll[0]=fl[4]; ll[1]=fl[5]; ll[2]=fl[6]; ll[3]=fl[7]; }
        else if (kq == 2) { ll[0]=fl[8]; ll[1]=0.f;  ll[2]=0.f;  ll[3]=0.f;  }
        else              { ll[0]=0.f;  ll[1]=0.f;  ll[2]=0.f;  ll[3]=0.f;  }

        uint32_t zhi[32], zlo[32];
        build_z(ll, rr, zhi, zlo);

        if (t + 1 < NT) {
            xl = xT[(size_t)(2 * p) * BDIM + b + 128];
            xr = xT[(size_t)(2 * p + 1) * BDIM + b + 128];
        }

        tile_body(c, t, NT, zhi, zlo, my_sttm, woff, kq, wid, dhalf, out, p, b);
    }
    tc_epilogue(c, NT, wid, tid, dhalf, out, p, (tile0 + NT - 1) * 128 + row_lane);

#else  // fp32 fallback
    float* sWf = reinterpret_cast<float*>(dyn);
    const int tid = threadIdx.x;
    const int p = blockIdx.x;
    const int tile0 = blockIdx.y * NT;
    const float fmin = *fminp;
    for (int idx = tid; idx < 4096; idx += 512) {
        int k = idx >> 4, d = idx & 15;
        int i = k >> 4, j = k & 15;
        sWf[idx] = (i < 9 && j < 9) ? W[(i * 9 + j) * 16 + d + (size_t)p * 9 * 9 * 16] : 0.f;
    }
    __syncthreads();
    const int g = tid >> 7, lane = tid & 127;
    for (int t = 0; t < NT; ++t) {
        int b = (tile0 + t) * 128 + lane;
        float l[16], r[16];
        fourier16(xT[(size_t)(2 * p) * BDIM + b], fmin, l);
        fourier16(xT[(size_t)(2 * p + 1) * BDIM + b], fmin, r);
        float a0 = 0.f, a1 = 0.f, a2 = 0.f, a3 = 0.f;
        #pragma unroll 4
        for (int i = 0; i < 16; ++i) {
            float li = l[i];
            #pragma unroll
            for (int j = 0; j < 16; ++j) {
                float lr = li * r[j];
                const float* w = sWf + ((i * 16 + j) << 4) + (g << 2);
                a0 = fmaf(lr, w[0], a0); a1 = fmaf(lr, w[1], a1);
                a2 = fmaf(lr, w[2], a2); a3 = fmaf(lr, w[3], a3);
            }
        }
        float4* op = reinterpret_cast<float4*>(out + ((size_t)p * BDIM + b) * 16 + (g << 2));
        *op = make_float4(a0, a1, a2, a3);
    }
#endif
}

// ---------------- levels 1..6 (tc) --------------------------------------------
__global__ __launch_bounds__(512) __cluster_dims__(1, 1, 1)
void tt_tc_level(const float* __restrict__ in,
                 const float* __restrict__ W,
                 float* __restrict__ out, int NT) {
    extern __shared__ char dyn[];
#if TC_PATH
    __shared__ uint32_t s_tmem[1];
    __shared__ __align__(16) unsigned long long s_mbar[2];
    char* sBhi = (char*)(((uintptr_t)dyn + 1023) & ~(uintptr_t)1023);
    char* sBlo = sBhi + 8192;

    const int tid = threadIdx.x;
    const int wid = tid >> 5;
    const int row_lane = tid & 127;
    const int kq = tid >> 7;
    const int p = blockIdx.x;
    const int tile0 = blockIdx.y * NT;

    if (wid == 0) { TC_ALLOC(smem_u32(s_tmem), 512); TC_RELINQ(); }
    if (tid == 0) { MBAR_INIT(smem_u32(&s_mbar[0]), 1); MBAR_INIT(smem_u32(&s_mbar[1]), 1); }
    stage_W(W, p, 16, sBhi, sBlo, tid);
    __syncthreads();

    TcCtx c;
    c.tmem = s_tmem[0];
    c.mbar_lo = smem_u32(&s_mbar[0]);
    c.mbar_main = smem_u32(&s_mbar[1]);
    c.dhi = make_desc(smem_u32(sBhi));
    c.dlo = make_desc(smem_u32(sBlo));
    c.nsteps = 16;
    const uint32_t woff = (uint32_t)(wid & 3) << 21;
    const int dhalf = (wid >> 2) & 1;

    InRegs cur = load_in(in, p, tile0 * 128 + row_lane, kq);

    for (int t = 0; t < NT; ++t) {
        const int b = (tile0 + t) * 128 + row_lane;

        float rr[16] = { cur.r0.x, cur.r0.y, cur.r0.z, cur.r0.w,
                         cur.r1.x, cur.r1.y, cur.r1.z, cur.r1.w,
                         cur.r2.x, cur.r2.y, cur.r2.z, cur.r2.w,
                         cur.r3.x, cur.r3.y, cur.r3.z, cur.r3.w };
        float ll[4] = { cur.lv.x, cur.lv.y, cur.lv.z, cur.lv.w };
        uint32_t zhi[32], zlo[32];
        build_z(ll, rr, zhi, zlo);

        InRegs nxt;
        if (t + 1 < NT) nxt = load_in(in, p, b + 128, kq);

        tile_body(c, t, NT, zhi, zlo, true, woff, kq, wid, dhalf, out, p, b);

        cur = nxt;
    }
    tc_epilogue(c, NT, wid, tid, dhalf, out, p, (tile0 + NT - 1) * 128 + row_lane);

#else  // fp32 fallback
    float* sWf = reinterpret_cast<float*>(dyn);
    const int tid = threadIdx.x;
    const int p = blockIdx.x;
    const int tile0 = blockIdx.y * NT;
    for (int idx = tid; idx < 4096; idx += 512)
        sWf[idx] = W[(size_t)p * 4096 + idx];
    __syncthreads();
    const int g = tid >> 7, lane = tid & 127;
    for (int t = 0; t < NT; ++t) {
        int b = (tile0 + t) * 128 + lane;
        float l[16], r[16];
        const float4* lp = reinterpret_cast<const float4*>(in + ((size_t)(2 * p)     * BDIM + b) * 16);
        const float4* rp = reinterpret_cast<const float4*>(in + ((size_t)(2 * p + 1) * BDIM + b) * 16);
        #pragma unroll
        for (int k = 0; k < 4; ++k) {
            float4 v = lp[k]; l[4*k] = v.x; l[4*k+1] = v.y; l[4*k+2] = v.z; l[4*k+3] = v.w;
            float4 u = rp[k]; r[4*k] = u.x; r[4*k+1] = u.y; r[4*k+2] = u.z; r[4*k+3] = u.w;
        }
        float a0 = 0.f, a1 = 0.f, a2 = 0.f, a3 = 0.f;
        #pragma unroll 4
        for (int i = 0; i < 16; ++i) {
            float li = l[i];
            #pragma unroll
            for (int j = 0; j < 16; ++j) {
                float lr = li * r[j];
                const float* w = sWf + ((i * 16 + j) << 4) + (g << 2);
                a0 = fmaf(lr, w[0], a0); a1 = fmaf(lr, w[1], a1);
                a2 = fmaf(lr, w[2], a2); a3 = fmaf(lr, w[3], a3);
            }
        }
        float4* op = reinterpret_cast<float4*>(out + ((size_t)p * BDIM + b) * 16 + (g << 2));
        *op = make_float4(a0, a1, a2, a3);
    }
#endif
}

// ---------------- level 7: 16x16 -> scalar ----------------------------------
__global__ __launch_bounds__(128) void tt_level7(const float* __restrict__ in,
                                                 const float* __restrict__ W,
                                                 float* __restrict__ out) {
    __shared__ float sW[BOND * BOND];
    const int tid = threadIdx.x;
    if (tid < BOND * BOND / 2)
        reinterpret_cast<float2*>(sW)[tid] = reinterpret_cast<const float2*>(W)[tid];
    __syncthreads();

    const int b = blockIdx.x * 128 + tid;
    float l[BOND], r[BOND];
    const float4* lp = reinterpret_cast<const float4*>(in + ((size_t)0 * BDIM + b) * BOND);
    const float4* rp = reinterpret_cast<const float4*>(in + ((size_t)1 * BDIM + b) * BOND);
    #pragma unroll
    for (int k = 0; k < 4; ++k) {
        float4 v = lp[k]; l[4*k] = v.x; l[4*k+1] = v.y; l[4*k+2] = v.z; l[4*k+3] = v.w;
        float4 u = rp[k]; r[4*k] = u.x; r[4*k+1] = u.y; r[4*k+2] = u.z; r[4*k+3] = u.w;
    }
    float acc = 0.f;
    #pragma unroll
    for (int i = 0; i < BOND; ++i) {
        float t = 0.f;
        #pragma unroll
        for (int j = 0; j < BOND; ++j) t = fmaf(sW[i * BOND + j], r[j], t);
        acc = fmaf(l[i], t, acc);
    }
    out[b] = acc;
}

// --------------------------------- launch -----------------------------------
extern "C" void kernel_launch(void* const* d_in, const int* in_sizes, int n_in,
                              void* d_out, int out_size) {
    const float* x    = (const float*)d_in[0];
    const float* fmin = (const float*)d_in[1];
    const float* W[8];
    for (int i = 0; i < 8; ++i) W[i] = (const float*)d_in[2 + i];

    float *xT, *bufA, *bufB;
    cudaGetSymbolAddress((void**)&xT,   g_xT);
    cudaGetSymbolAddress((void**)&bufA, g_bufA);
    cudaGetSymbolAddress((void**)&bufB, g_bufB);

    cudaFuncSetAttribute(tt_tc_level0, cudaFuncAttributeMaxDynamicSharedMemorySize, SMEM_DYN);
    cudaFuncSetAttribute(tt_tc_level,  cudaFuncAttributeMaxDynamicSharedMemorySize, SMEM_DYN);

    tt_transpose<<<dim3(FDIM / 32, BDIM / 32), dim3(32, 8)>>>(x, xT);

    tt_tc_level0<<<dim3(128,  8), 512, SMEM_DYN>>>(xT, fmin, W[0], bufA, 16); // 1024 CTAs
    tt_tc_level <<<dim3( 64,  8), 512, SMEM_DYN>>>(bufA, W[1], bufB, 16);     //  512
    tt_tc_level <<<dim3( 32, 16), 512, SMEM_DYN>>>(bufB, W[2], bufA,  8);     //  512
    tt_tc_level <<<dim3( 16, 32), 512, SMEM_DYN>>>(bufA, W[3], bufB,  4);     //  512
    tt_tc_level <<<dim3(  8, 64), 512, SMEM_DYN>>>(bufB, W[4], bufA,  2);     //  512
    tt_tc_level <<<dim3(  4,128), 512, SMEM_DYN>>>(bufA, W[5], bufB,  1);     //  512
    tt_tc_level <<<dim3(  2,128), 512, SMEM_DYN>>>(bufB, W[6], bufA,  1);     //  256
    tt_level7<<<BDIM / 128, 128>>>(bufA, W[7], (float*)d_out);
}

// round 17
// speedup vs baseline: 1.0545x; 1.0545x over previous
#include <cuda_runtime.h>
#include <cuda_bf16.h>
#include <cstdint>

#define BDIM   16384
#define FDIM   256
#define BOND   16

#if defined(__CUDA_ARCH__) && (defined(__CUDA_ARCH_FEAT_SM103_ALL) || defined(__CUDA_ARCH_SPECIFIC__))
#define TC_PATH 1
#else
#define TC_PATH 0
#endif

// 130 KB dynamic smem -> exactly one CTA per SM (TMEM 512-col alloc safety).
#define SMEM_DYN (130 * 1024)

__device__ float g_xT[FDIM * BDIM];
__device__ float g_bufA[128 * BDIM * BOND];
__device__ float g_bufB[64  * BDIM * BOND];

#if TC_PATH
__device__ __forceinline__ uint32_t smem_u32(const void* p) {
    uint32_t a;
    asm("{ .reg .u64 t; cvta.to.shared.u64 t, %1; cvt.u32.u64 %0, t; }" : "=r"(a) : "l"(p));
    return a;
}
__device__ __forceinline__ uint32_t elect_one() {
    uint32_t p;
    asm volatile("{ .reg .pred p; elect.sync _|p, 0xFFFFFFFF; selp.b32 %0, 1, 0, p; }" : "=r"(p));
    return p;
}
#define TC_ALLOC(smem_addr, n) \
    asm volatile("tcgen05.alloc.cta_group::1.sync.aligned.shared::cta.b32 [%0], %1;" \
                 :: "r"(smem_addr), "r"((uint32_t)(n)) : "memory")
#define TC_DEALLOC(tmem, n) \
    asm volatile("tcgen05.dealloc.cta_group::1.sync.aligned.b32 %0, %1;" :: "r"(tmem), "r"((uint32_t)(n)))
#define TC_RELINQ() \
    asm volatile("tcgen05.relinquish_alloc_permit.cta_group::1.sync.aligned;")
#define TC_WAIT_ST() asm volatile("tcgen05.wait::st.sync.aligned;" ::: "memory")
#define TC_WAIT_LD() asm volatile("tcgen05.wait::ld.sync.aligned;" ::: "memory")
#define TC_FENCE_BEFORE() asm volatile("tcgen05.fence::before_thread_sync;" ::: "memory")
#define TC_FENCE_AFTER()  asm volatile("tcgen05.fence::after_thread_sync;" ::: "memory")
#define TC_COMMIT(mbar) \
    asm volatile("tcgen05.commit.cta_group::1.mbarrier::arrive::one.shared::cluster.b64 [%0];" \
                 :: "r"(mbar) : "memory")
#define MBAR_INIT(mbar, cnt) \
    asm volatile("mbarrier.init.shared.b64 [%0], %1;" :: "r"(mbar), "r"((uint32_t)(cnt)) : "memory")
#define MBAR_INVAL(mbar) \
    asm volatile("mbarrier.inval.shared.b64 [%0];" :: "r"(mbar) : "memory")
#define MBAR_WAIT(mbar, parity) do {                                             \
    uint32_t _m = (mbar); uint32_t _p = (parity); uint32_t _done;                \
    asm volatile("{ .reg .pred p; mbarrier.try_wait.parity.acquire.cta.shared::cta.b64 p, [%1], %2;" \
                 " selp.b32 %0, 1, 0, p; }" : "=r"(_done) : "r"(_m), "r"(_p) : "memory"); \
    if (!_done) {                                                                \
        asm volatile("{ .reg .pred P1; WL%=:"                                    \
                     " mbarrier.try_wait.parity.acquire.cta.shared::cta.b64 P1, [%0], %1, 0x989680;" \
                     " @P1 bra.uni WD%=; bra.uni WL%=; WD%=: }"                  \
                     :: "r"(_m), "r"(_p) : "memory");                            \
    } } while (0)

__device__ __forceinline__ void sttm_x32(uint32_t addr, const uint32_t* r) {
    asm volatile(
        "tcgen05.st.sync.aligned.32x32b.x32.b32 [%0], "
        "{%1,%2,%3,%4,%5,%6,%7,%8,%9,%10,%11,%12,%13,%14,%15,%16,"
        "%17,%18,%19,%20,%21,%22,%23,%24,%25,%26,%27,%28,%29,%30,%31,%32};"
        :: "r"(addr),
           "r"(r[0]),"r"(r[1]),"r"(r[2]),"r"(r[3]),"r"(r[4]),"r"(r[5]),"r"(r[6]),"r"(r[7]),
           "r"(r[8]),"r"(r[9]),"r"(r[10]),"r"(r[11]),"r"(r[12]),"r"(r[13]),"r"(r[14]),"r"(r[15]),
           "r"(r[16]),"r"(r[17]),"r"(r[18]),"r"(r[19]),"r"(r[20]),"r"(r[21]),"r"(r[22]),"r"(r[23]),
           "r"(r[24]),"r"(r[25]),"r"(r[26]),"r"(r[27]),"r"(r[28]),"r"(r[29]),"r"(r[30]),"r"(r[31])
        : "memory");
}
__device__ __forceinline__ void sttm_x8(uint32_t addr, const uint32_t* r) {
    asm volatile(
        "tcgen05.st.sync.aligned.32x32b.x8.b32 [%0], "
        "{%1,%2,%3,%4,%5,%6,%7,%8};"
        :: "r"(addr),
           "r"(r[0]),"r"(r[1]),"r"(r[2]),"r"(r[3]),
           "r"(r[4]),"r"(r[5]),"r"(r[6]),"r"(r[7])
        : "memory");
}
__device__ __forceinline__ void ldtm_x8(uint32_t* r, uint32_t addr) {
    asm volatile(
        "tcgen05.ld.sync.aligned.32x32b.x8.b32 "
        "{%0,%1,%2,%3,%4,%5,%6,%7}, [%8];"
        : "=r"(r[0]),"=r"(r[1]),"=r"(r[2]),"=r"(r[3]),
          "=r"(r[4]),"=r"(r[5]),"=r"(r[6]),"=r"(r[7])
        : "r"(addr));
}
__device__ __forceinline__ void mma_f16_ts(uint32_t d_tmem, uint32_t a_tmem,
                                           uint64_t b_desc, uint32_t idesc, bool acc) {
    uint32_t en = acc ? 1u : 0u;
    asm volatile(
        "{ .reg .pred p; setp.ne.u32 p, %5, 0;"
        " tcgen05.mma.cta_group::1.kind::f16 [%0], [%1], %2, %3, {%4,%4,%4,%4}, p; }"
        :: "r"(d_tmem), "r"(a_tmem), "l"(b_desc), "r"(idesc), "r"(0u), "r"(en)
        : "memory");
}
__device__ __forceinline__ uint64_t make_desc(uint32_t smem_addr) {
    return ((uint64_t)2 << 61) | ((uint64_t)1 << 46) | ((uint64_t)64 << 32)
         | ((uint64_t)1 << 16) | (((uint64_t)(smem_addr >> 4)) & 0x3FFF);
}

// Drain half of a 16-col D buffer (8 d-columns) to global. Warps 0-7:
// half = wid>>2 (0: cols 0-7, 1: cols 8-15); subpartition = wid&3.
__device__ __forceinline__ void drain_D_half(float* __restrict__ out, int p, int bp,
                                             uint32_t tDbuf, int half) {
    uint32_t dr[8];
    ldtm_x8(dr, tDbuf + (uint32_t)(half * 8));
    TC_WAIT_LD();
    float4* op = reinterpret_cast<float4*>(out + ((size_t)p * BDIM + bp) * 16 + half * 8);
    op[0] = make_float4(__uint_as_float(dr[0]), __uint_as_float(dr[1]),
                        __uint_as_float(dr[2]), __uint_as_float(dr[3]));
    op[1] = make_float4(__uint_as_float(dr[4]), __uint_as_float(dr[5]),
                        __uint_as_float(dr[6]), __uint_as_float(dr[7]));
}

// Stage W as bf16 hi/lo, N=16 rows x K=256, K-major blocked-atom SW128.
__device__ __forceinline__ void stage_W(const float* __restrict__ W, int p, int kin,
                                        char* sBhi, char* sBlo, int tid) {
    for (int idx = tid; idx < 4096; idx += 512) {
        int k = idx >> 4, d = idx & 15;
        int i = k >> 4, j = k & 15;
        float w = (i < kin && j < kin)
                ? W[(size_t)p * kin * kin * 16 + ((i * kin + j) * 16 + d)] : 0.f;
        __nv_bfloat16 h  = __float2bfloat16(w);
        __nv_bfloat16 lo = __float2bfloat16(w - __bfloat162float(h));
        int atom = (d >> 3) + (k >> 6) * 2;
        uint32_t off = (uint32_t)atom * 1024u + (uint32_t)(d & 7) * 128u + (uint32_t)(k & 63) * 2u;
        uint32_t sw = off ^ ((off >> 3) & 0x70);
        *reinterpret_cast<__nv_bfloat16*>(sBhi + sw) = h;
        *reinterpret_cast<__nv_bfloat16*>(sBlo + sw) = lo;
    }
}

// z pair build: hi = rn_bf16x2(z), residual exact via bit-recovered hi.
__device__ __forceinline__ void z_pair(float z0, float z1, uint32_t& h2, uint32_t& l2) {
    asm("cvt.rn.bf16x2.f32 %0, %1, %2;" : "=r"(h2) : "f"(z1), "f"(z0));
    float hf0 = __uint_as_float(h2 << 16);
    float hf1 = __uint_as_float(h2 & 0xffff0000u);
    float zl0 = z0 - hf0;
    float zl1 = z1 - hf1;
    asm("cvt.rn.bf16x2.f32 %0, %1, %2;" : "=r"(l2) : "f"(zl1), "f"(zl0));
}

__device__ __forceinline__ void build_z(const float* ll, const float* rr,
                                        uint32_t* zhi, uint32_t* zlo) {
    #pragma unroll
    for (int ii = 0; ii < 4; ++ii) {
        #pragma unroll
        for (int jh = 0; jh < 8; ++jh) {
            z_pair(ll[ii] * rr[2 * jh], ll[ii] * rr[2 * jh + 1],
                   zhi[ii * 8 + jh], zlo[ii * 8 + jh]);
        }
    }
}
// Single-l variant (16 values = 8 pairs) for L0 kq2.
__device__ __forceinline__ void build_z1(float l0, const float* rr,
                                         uint32_t* zhi, uint32_t* zlo) {
    #pragma unroll
    for (int jh = 0; jh < 8; ++jh) {
        z_pair(l0 * rr[2 * jh], l0 * rr[2 * jh + 1], zhi[jh], zlo[jh]);
    }
}
#endif // TC_PATH

struct InRegs { float4 lv, r0, r1, r2, r3; };
__device__ __forceinline__ InRegs load_in(const float* __restrict__ in,
                                          int p, int b, int kq) {
    InRegs q;
    const float4* lp = reinterpret_cast<const float4*>(in + ((size_t)(2 * p) * BDIM + b) * 16);
    q.lv = lp[kq];
    const float4* rp = reinterpret_cast<const float4*>(in + ((size_t)(2 * p + 1) * BDIM + b) * 16);
    q.r0 = rp[0]; q.r1 = rp[1]; q.r2 = rp[2]; q.r3 = rp[3];
    return q;
}

// ---------------- x transpose ------------------------------------------------
__global__ __launch_bounds__(256) void tt_transpose(const float* __restrict__ x,
                                                    float* __restrict__ xT) {
    __shared__ float tile[32][33];
    const int c0 = blockIdx.x * 32;
    const int r0 = blockIdx.y * 32;
    #pragma unroll
    for (int k = 0; k < 4; ++k) {
        int r = r0 + threadIdx.y + 8 * k;
        tile[threadIdx.y + 8 * k][threadIdx.x] = x[(size_t)r * FDIM + c0 + threadIdx.x];
    }
    __syncthreads();
    #pragma unroll
    for (int k = 0; k < 4; ++k) {
        int c = c0 + threadIdx.y + 8 * k;
        xT[(size_t)c * BDIM + r0 + threadIdx.x] = tile[threadIdx.x][threadIdx.y + 8 * k];
    }
}

__device__ __forceinline__ void fourier16(float xv, float fmin, float* f) {
    float a = xv * fmin;
    float s1, c1;
    __sincosf(a, &s1, &c1);
    float s2 = 2.f * s1 * c1,       c2 = c1 * c1 - s1 * s1;
    float s3 = s2 * c1 + c2 * s1,   c3 = c2 * c1 - s2 * s1;
    float s4 = s3 * c1 + c3 * s1,   c4 = c3 * c1 - s3 * s1;
    f[0] = 1.f; f[1] = s1; f[2] = s2; f[3] = s3; f[4] = s4;
    f[5] = c1;  f[6] = c2; f[7] = c3; f[8] = c4;
    #pragma unroll
    for (int i = 9; i < 16; ++i) f[i] = 0.f;
}

// ---------------- level 0 (tc) -----------------------------------------------
// kq0/kq1: full 64-value z build + 2x sttm_x32.
// kq2: MMA only reads k<144 -> cols 64-71 of its block; build 16 values + 2x sttm_x8.
// kq3: never read by the 9-step MMA; no build, no STTM.
__global__ __launch_bounds__(512) __cluster_dims__(1, 1, 1)
void tt_tc_level0(const float* __restrict__ xT,
                  const float* __restrict__ fminp,
                  const float* __restrict__ W,
                  float* __restrict__ out, int NT) {
    extern __shared__ char dyn[];
#if TC_PATH
    __shared__ uint32_t s_tmem[1];
    __shared__ __align__(8) unsigned long long s_mbar;
    char* sBhi = (char*)(((uintptr_t)dyn + 1023) & ~(uintptr_t)1023);
    char* sBlo = sBhi + 8192;

    const int tid = threadIdx.x;
    const int wid = tid >> 5;
    const int row_lane = tid & 127;
    const int kq = tid >> 7;
    const int p = blockIdx.x;
    const int tile0 = blockIdx.y * NT;
    const float fmin = *fminp;

    if (wid == 0) { TC_ALLOC(smem_u32(s_tmem), 512); TC_RELINQ(); }
    if (tid == 0) { MBAR_INIT(smem_u32(&s_mbar), 1); }
    stage_W(W, p, 9, sBhi, sBlo, tid);
    __syncthreads();

    const uint32_t mbar = smem_u32(&s_mbar);
    const uint32_t tmem = s_tmem[0];
    const uint32_t tD = tmem + 256;          // two 16-col D buffers
    const uint64_t dhi = make_desc(smem_u32(sBhi));
    const uint64_t dlo = make_desc(smem_u32(sBlo));
    const uint32_t IDESC = 0x8040490u;       // F32 acc, bf16 a/b, M=128, N=16
    const uint32_t woff = (uint32_t)(wid & 3) << 21;
    const int dhalf = (wid >> 2) & 1;

    float xl = xT[(size_t)(2 * p) * BDIM + tile0 * 128 + row_lane];
    float xr = xT[(size_t)(2 * p + 1) * BDIM + tile0 * 128 + row_lane];

    for (int t = 0; t < NT; ++t) {
        const int b = (tile0 + t) * 128 + row_lane;

        uint32_t zhi[32], zlo[32];
        if (kq < 3) {
            float rr[16]; fourier16(xr, fmin, rr);
            float fl[16]; fourier16(xl, fmin, fl);
            if (kq == 0) {
                float ll[4] = { fl[0], fl[1], fl[2], fl[3] };
                build_z(ll, rr, zhi, zlo);
            } else if (kq == 1) {
                float ll[4] = { fl[4], fl[5], fl[6], fl[7] };
                build_z(ll, rr, zhi, zlo);
            } else {
                build_z1(fl[8], rr, zhi, zlo);   // only first 8 pairs valid
            }
        }

        if (t + 1 < NT) {
            xl = xT[(size_t)(2 * p) * BDIM + b + 128];
            xr = xT[(size_t)(2 * p + 1) * BDIM + b + 128];
        }

        if (t > 0) { MBAR_WAIT(mbar, (uint32_t)((t - 1) & 1)); TC_FENCE_AFTER(); }

        if (kq < 2) {
            sttm_x32(tmem + woff + (uint32_t)(kq * 32), zhi);
            sttm_x32(tmem + woff + 128u + (uint32_t)(kq * 32), zlo);
        } else if (kq == 2) {
            sttm_x8(tmem + woff + 64u, zhi);
            sttm_x8(tmem + woff + 128u + 64u, zlo);
        }
        if (t > 0 && wid < 8)
            drain_D_half(out, p, b - 128, tD + (uint32_t)(((t - 1) & 1) * 16), dhalf);
        TC_WAIT_ST();
        TC_FENCE_BEFORE();
        __syncthreads();

        if (wid == 8 && elect_one()) {
            TC_FENCE_AFTER();
            uint32_t tDbuf = tD + (uint32_t)((t & 1) * 16);
            #pragma unroll 1
            for (int term = 0; term < 3; ++term) {
                uint32_t ab = tmem + ((term == 2) ? 128u : 0u);
                uint64_t bd = (term == 1) ? dlo : dhi;
                for (int s = 0; s < 9; ++s) {
                    uint64_t bdesc = bd + (uint64_t)((s >> 2) * 128 + (s & 3) * 2);
                    mma_f16_ts(tDbuf, ab + (uint32_t)(s * 8), bdesc, IDESC,
                               !(term == 0 && s == 0));
                }
            }
            TC_COMMIT(mbar);
        }
    }

    MBAR_WAIT(mbar, (uint32_t)((NT - 1) & 1));
    TC_FENCE_AFTER();
    if (wid < 8)
        drain_D_half(out, p, (tile0 + NT - 1) * 128 + row_lane,
                     tD + (uint32_t)(((NT - 1) & 1) * 16), dhalf);
    __syncthreads();
    if (tid == 0) { MBAR_INVAL(mbar); }
    __syncthreads();
    if (wid == 0) { TC_DEALLOC(tmem, 512); }

#else  // fp32 fallback
    float* sWf = reinterpret_cast<float*>(dyn);
    const int tid = threadIdx.x;
    const int p = blockIdx.x;
    const int tile0 = blockIdx.y * NT;
    const float fmin = *fminp;
    for (int idx = tid; idx < 4096; idx += 512) {
        int k = idx >> 4, d = idx & 15;
        int i = k >> 4, j = k & 15;
        sWf[idx] = (i < 9 && j < 9) ? W[(i * 9 + j) * 16 + d + (size_t)p * 9 * 9 * 16] : 0.f;
    }
    __syncthreads();
    const int g = tid >> 7, lane = tid & 127;
    for (int t = 0; t < NT; ++t) {
        int b = (tile0 + t) * 128 + lane;
        float l[16], r[16];
        fourier16(xT[(size_t)(2 * p) * BDIM + b], fmin, l);
        fourier16(xT[(size_t)(2 * p + 1) * BDIM + b], fmin, r);
        float a0 = 0.f, a1 = 0.f, a2 = 0.f, a3 = 0.f;
        #pragma unroll 4
        for (int i = 0; i < 16; ++i) {
            float li = l[i];
            #pragma unroll
            for (int j = 0; j < 16; ++j) {
                float lr = li * r[j];
                const float* w = sWf + ((i * 16 + j) << 4) + (g << 2);
                a0 = fmaf(lr, w[0], a0); a1 = fmaf(lr, w[1], a1);
                a2 = fmaf(lr, w[2], a2); a3 = fmaf(lr, w[3], a3);
            }
        }
        float4* op = reinterpret_cast<float4*>(out + ((size_t)p * BDIM + b) * 16 + (g << 2));
        *op = make_float4(a0, a1, a2, a3);
    }
#endif
}

// ---------------- levels 1..6 (tc) — byte-identical to the 385us R14 ----------
__global__ __launch_bounds__(512) __cluster_dims__(1, 1, 1)
void tt_tc_level(const float* __restrict__ in,
                 const float* __restrict__ W,
                 float* __restrict__ out, int NT) {
    extern __shared__ char dyn[];
#if TC_PATH
    __shared__ uint32_t s_tmem[1];
    __shared__ __align__(8) unsigned long long s_mbar;
    char* sBhi = (char*)(((uintptr_t)dyn + 1023) & ~(uintptr_t)1023);
    char* sBlo = sBhi + 8192;

    const int tid = threadIdx.x;
    const int wid = tid >> 5;
    const int row_lane = tid & 127;
    const int kq = tid >> 7;
    const int p = blockIdx.x;
    const int tile0 = blockIdx.y * NT;

    if (wid == 0) { TC_ALLOC(smem_u32(s_tmem), 512); TC_RELINQ(); }
    if (tid == 0) { MBAR_INIT(smem_u32(&s_mbar), 1); }
    stage_W(W, p, 16, sBhi, sBlo, tid);
    __syncthreads();

    const uint32_t mbar = smem_u32(&s_mbar);
    const uint32_t tmem = s_tmem[0];
    const uint32_t tD = tmem + 256;
    const uint64_t dhi = make_desc(smem_u32(sBhi));
    const uint64_t dlo = make_desc(smem_u32(sBlo));
    const uint32_t IDESC = 0x8040490u;       // N=16
    const uint32_t woff = (uint32_t)(wid & 3) << 21;
    const int dhalf = (wid >> 2) & 1;

    InRegs cur = load_in(in, p, tile0 * 128 + row_lane, kq);

    for (int t = 0; t < NT; ++t) {
        const int b = (tile0 + t) * 128 + row_lane;

        float rr[16] = { cur.r0.x, cur.r0.y, cur.r0.z, cur.r0.w,
                         cur.r1.x, cur.r1.y, cur.r1.z, cur.r1.w,
                         cur.r2.x, cur.r2.y, cur.r2.z, cur.r2.w,
                         cur.r3.x, cur.r3.y, cur.r3.z, cur.r3.w };
        float ll[4] = { cur.lv.x, cur.lv.y, cur.lv.z, cur.lv.w };
        uint32_t zhi[32], zlo[32];
        build_z(ll, rr, zhi, zlo);

        InRegs nxt;
        if (t + 1 < NT) nxt = load_in(in, p, b + 128, kq);

        if (t > 0) { MBAR_WAIT(mbar, (uint32_t)((t - 1) & 1)); TC_FENCE_AFTER(); }

        sttm_x32(tmem + woff + (uint32_t)(kq * 32), zhi);
        sttm_x32(tmem + woff + 128u + (uint32_t)(kq * 32), zlo);
        if (t > 0 && wid < 8)
            drain_D_half(out, p, b - 128, tD + (uint32_t)(((t - 1) & 1) * 16), dhalf);
        TC_WAIT_ST();
        TC_FENCE_BEFORE();
        __syncthreads();

        if (wid == 8 && elect_one()) {
            TC_FENCE_AFTER();
            uint32_t tDbuf = tD + (uint32_t)((t & 1) * 16);
            #pragma unroll 1
            for (int term = 0; term < 3; ++term) {
                uint32_t ab = tmem + ((term == 2) ? 128u : 0u);
                uint64_t bd = (term == 1) ? dlo : dhi;
                #pragma unroll
                for (int s = 0; s < 16; ++s) {
                    uint64_t bdesc = bd + (uint64_t)((s >> 2) * 128 + (s & 3) * 2);
                    mma_f16_ts(tDbuf, ab + (uint32_t)(s * 8), bdesc, IDESC,
                               !(term == 0 && s == 0));
                }
            }
            TC_COMMIT(mbar);
        }

        cur = nxt;
    }

    MBAR_WAIT(mbar, (uint32_t)((NT - 1) & 1));
    TC_FENCE_AFTER();
    if (wid < 8)
        drain_D_half(out, p, (tile0 + NT - 1) * 128 + row_lane,
                     tD + (uint32_t)(((NT - 1) & 1) * 16), dhalf);
    __syncthreads();
    if (tid == 0) { MBAR_INVAL(mbar); }
    __syncthreads();
    if (wid == 0) { TC_DEALLOC(tmem, 512); }

#else  // fp32 fallback
    float* sWf = reinterpret_cast<float*>(dyn);
    const int tid = threadIdx.x;
    const int p = blockIdx.x;
    const int tile0 = blockIdx.y * NT;
    for (int idx = tid; idx < 4096; idx += 512)
        sWf[idx] = W[(size_t)p * 4096 + idx];
    __syncthreads();
    const int g = tid >> 7, lane = tid & 127;
    for (int t = 0; t < NT; ++t) {
        int b = (tile0 + t) * 128 + lane;
        float l[16], r[16];
        const float4* lp = reinterpret_cast<const float4*>(in + ((size_t)(2 * p)     * BDIM + b) * 16);
        const float4* rp = reinterpret_cast<const float4*>(in + ((size_t)(2 * p + 1) * BDIM + b) * 16);
        #pragma unroll
        for (int k = 0; k < 4; ++k) {
            float4 v = lp[k]; l[4*k] = v.x; l[4*k+1] = v.y; l[4*k+2] = v.z; l[4*k+3] = v.w;
            float4 u = rp[k]; r[4*k] = u.x; r[4*k+1] = u.y; r[4*k+2] = u.z; r[4*k+3] = u.w;
        }
        float a0 = 0.f, a1 = 0.f, a2 = 0.f, a3 = 0.f;
        #pragma unroll 4
        for (int i = 0; i < 16; ++i) {
            float li = l[i];
            #pragma unroll
            for (int j = 0; j < 16; ++j) {
                float lr = li * r[j];
                const float* w = sWf + ((i * 16 + j) << 4) + (g << 2);
                a0 = fmaf(lr, w[0], a0); a1 = fmaf(lr, w[1], a1);
                a2 = fmaf(lr, w[2], a2); a3 = fmaf(lr, w[3], a3);
            }
        }
        float4* op = reinterpret_cast<float4*>(out + ((size_t)p * BDIM + b) * 16 + (g << 2));
        *op = make_float4(a0, a1, a2, a3);
    }
#endif
}

// ---------------- level 7: 16x16 -> scalar ----------------------------------
__global__ __launch_bounds__(128) void tt_level7(const float* __restrict__ in,
                                                 const float* __restrict__ W,
                                                 float* __restrict__ out) {
    __shared__ float sW[BOND * BOND];
    const int tid = threadIdx.x;
    if (tid < BOND * BOND / 2)
        reinterpret_cast<float2*>(sW)[tid] = reinterpret_cast<const float2*>(W)[tid];
    __syncthreads();

    const int b = blockIdx.x * 128 + tid;
    float l[BOND], r[BOND];
    const float4* lp = reinterpret_cast<const float4*>(in + ((size_t)0 * BDIM + b) * BOND);
    const float4* rp = reinterpret_cast<const float4*>(in + ((size_t)1 * BDIM + b) * BOND);
    #pragma unroll
    for (int k = 0; k < 4; ++k) {
        float4 v = lp[k]; l[4*k] = v.x; l[4*k+1] = v.y; l[4*k+2] = v.z; l[4*k+3] = v.w;
        float4 u = rp[k]; r[4*k] = u.x; r[4*k+1] = u.y; r[4*k+2] = u.z; r[4*k+3] = u.w;
    }
    float acc = 0.f;
    #pragma unroll
    for (int i = 0; i < BOND; ++i) {
        float t = 0.f;
        #pragma unroll
        for (int j = 0; j < BOND; ++j) t = fmaf(sW[i * BOND + j], r[j], t);
        acc = fmaf(l[i], t, acc);
    }
    out[b] = acc;
}

// --------------------------------- launch -----------------------------------
extern "C" void kernel_launch(void* const* d_in, const int* in_sizes, int n_in,
                              void* d_out, int out_size) {
    const float* x    = (const float*)d_in[0];
    const float* fmin = (const float*)d_in[1];
    const float* W[8];
    for (int i = 0; i < 8; ++i) W[i] = (const float*)d_in[2 + i];

    float *xT, *bufA, *bufB;
    cudaGetSymbolAddress((void**)&xT,   g_xT);
    cudaGetSymbolAddress((void**)&bufA, g_bufA);
    cudaGetSymbolAddress((void**)&bufB, g_bufB);

    cudaFuncSetAttribute(tt_tc_level0, cudaFuncAttributeMaxDynamicSharedMemorySize, SMEM_DYN);
    cudaFuncSetAttribute(tt_tc_level,  cudaFuncAttributeMaxDynamicSharedMemorySize, SMEM_DYN);

    tt_transpose<<<dim3(FDIM / 32, BDIM / 32), dim3(32, 8)>>>(x, xT);

    tt_tc_level0<<<dim3(128,  8), 512, SMEM_DYN>>>(xT, fmin, W[0], bufA, 16); // 1024 CTAs
    tt_tc_level <<<dim3( 64,  8), 512, SMEM_DYN>>>(bufA, W[1], bufB, 16);     //  512
    tt_tc_level <<<dim3( 32, 16), 512, SMEM_DYN>>>(bufB, W[2], bufA,  8);     //  512
    tt_tc_level <<<dim3( 16, 32), 512, SMEM_DYN>>>(bufA, W[3], bufB,  4);     //  512
    tt_tc_level <<<dim3(  8, 64), 512, SMEM_DYN>>>(bufB, W[4], bufA,  2);     //  512
    tt_tc_level <<<dim3(  4,128), 512, SMEM_DYN>>>(bufA, W[5], bufB,  1);     //  512
    tt_tc_level <<<dim3(  2,128), 512, SMEM_DYN>>>(bufB, W[6], bufA,  1);     //  256
    tt_level7<<<BDIM / 128, 128>>>(bufA, W[7], (float*)d_out);
}